// round 17
// baseline (speedup 1.0000x reference)
#include <cuda_runtime.h>
#include <math.h>

// Problem constants
#define NTOKS 4096   // B*T
#define DIMV  512
#define QDV   2048   // 2*H*DH
#define HV    8
#define DHV   128
#define NKV   256
#define KKV   16

typedef unsigned long long ull;

// packed fp32x2 FMA (sm_103a FFMA2) — bit-exact fp32 per lane
#define FMA2(d, a, b) \
    asm("fma.rn.f32x2 %0, %1, %2, %0;" : "+l"(d) : "l"(a), "l"(b))
#define PACKDUP(out, x) \
    asm("mov.b64 %0, {%1, %1};" : "=l"(out) : "r"(__float_as_uint(x)))
#define UNPACK2(lo, hi, in) \
    asm("mov.b64 {%0, %1}, %2;" : "=r"(lo), "=r"(hi) : "l"(in))

// Scratch (allocation-free rule: __device__ globals)
__device__ __align__(16) float g_q[NTOKS * QDV];            // LN'd projected q
__device__ __align__(16) ull   g_scores[NTOKS * HV * 2 * 128]; // raw score pairs (64MB)
__device__ __align__(16) float g_attn[NTOKS * HV * KKV];    // softmax weights
__device__ __align__(16) int   g_vidx[NTOKS * HV * KKV];    // value row indices

// Stage-2 candidate tables: (i,j) with (i+1)(j+1) <= 16 — 50 candidates,
// provably a superset of the top-16 of sx[i]+sy[j] with sx,sy sorted desc
// (exact under the reference's lower-flattened-index tie-break).
__device__ __constant__ int c_ci[64] = {
    0,0,0,0,0,0,0,0,0,0,0,0,0,0,0,0,
    1,1,1,1,1,1,1,1,
    2,2,2,2,2,
    3,3,3,3,
    4,4,4,
    5,5, 6,6, 7,7,
    8,9,10,11,12,13,14,15,
    0,0,0,0,0,0,0,0,0,0,0,0,0,0};
__device__ __constant__ int c_cj[64] = {
    0,1,2,3,4,5,6,7,8,9,10,11,12,13,14,15,
    0,1,2,3,4,5,6,7,
    0,1,2,3,4,
    0,1,2,3,
    0,1,2,
    0,1, 0,1, 0,1,
    0,0,0,0,0,0,0,0,
    0,0,0,0,0,0,0,0,0,0,0,0,0,0};

// ---------------------------------------------------------------------------
// K1 (+fused LN): VERBATIM round 13 (541.2us best, 187us, 78 regs, 3 CTA/SM).
// ---------------------------------------------------------------------------
__global__ __launch_bounds__(256) void k1_gemm_ln(const float* __restrict__ X,
                                                  const float* __restrict__ W,
                                                  const float* __restrict__ gamma,
                                                  const float* __restrict__ beta)
{
    __shared__ float As[16][68];    // [k][m] 64 rows + pad
    __shared__ float Bs[16][132];   // [k][n] 128 rows + pad

    const int tid = threadIdx.x;
    const int tx = tid & 31;       // n-group: cols tx*4..tx*4+3
    const int ty = tid >> 5;       // m-group (warp id)
    const int m0 = blockIdx.x * 64;
    const int n0 = blockIdx.y * 128;   // exactly one (p,h) head slice

    ull acc[4][4];                 // [row-pair][col]
#pragma unroll
    for (int ip = 0; ip < 4; ip++)
#pragma unroll
        for (int j = 0; j < 4; j++) acc[ip][j] = 0ULL;

    const int arow = tid >> 2;          // 0..63
    const int akc  = (tid & 3) << 2;    // 0,4,8,12
    const int brow0 = tid >> 2;         // 0..63   (q=0)
    const int brow1 = 64 + (tid >> 2);  // 64..127 (q=1)

    const float* Abase = X + (size_t)(m0 + arow) * DIMV + akc;
    const float* Bbase0 = W + (size_t)(n0 + brow0) * DIMV + akc;
    const float* Bbase1 = W + (size_t)(n0 + brow1) * DIMV + akc;

    // prologue: prefetch tile kt=0
    float4 pa  = *(const float4*)(Abase);
    float4 pb0 = *(const float4*)(Bbase0);
    float4 pb1 = *(const float4*)(Bbase1);

    for (int kt = 0; kt < DIMV; kt += 16) {
        As[akc + 0][arow] = pa.x; As[akc + 1][arow] = pa.y;
        As[akc + 2][arow] = pa.z; As[akc + 3][arow] = pa.w;
        Bs[akc + 0][brow0] = pb0.x; Bs[akc + 1][brow0] = pb0.y;
        Bs[akc + 2][brow0] = pb0.z; Bs[akc + 3][brow0] = pb0.w;
        Bs[akc + 0][brow1] = pb1.x; Bs[akc + 1][brow1] = pb1.y;
        Bs[akc + 2][brow1] = pb1.z; Bs[akc + 3][brow1] = pb1.w;
        __syncthreads();

        if (kt + 16 < DIMV) {
            pa  = *(const float4*)(Abase + kt + 16);
            pb0 = *(const float4*)(Bbase0 + kt + 16);
            pb1 = *(const float4*)(Bbase1 + kt + 16);
        }

#pragma unroll 4
        for (int k = 0; k < 16; k++) {
            ulonglong2 a01 = *(const ulonglong2*)&As[k][ty * 4];
            ulonglong2 a23 = *(const ulonglong2*)&As[k][32 + ty * 4];
            ull av[4] = {a01.x, a01.y, a23.x, a23.y};
            float4 b = *(const float4*)&Bs[k][tx * 4];
            ull bd[4];
            PACKDUP(bd[0], b.x); PACKDUP(bd[1], b.y);
            PACKDUP(bd[2], b.z); PACKDUP(bd[3], b.w);
#pragma unroll
            for (int ip = 0; ip < 4; ip++)
#pragma unroll
                for (int j = 0; j < 4; j++)
                    FMA2(acc[ip][j], av[ip], bd[j]);
        }
        __syncthreads();
    }

    // epilogue: LN per row (exact k2 layout + reduction tree), then store.
    float4 g4 = *(const float4*)(gamma + tx * 4);
    float4 b4 = *(const float4*)(beta + tx * 4);

#pragma unroll
    for (int ip = 0; ip < 4; ip++) {
#pragma unroll
        for (int e = 0; e < 2; e++) {
            int row = (ip >> 1) * 32 + ty * 4 + (ip & 1) * 2 + e;
            float4 v;
            {
                unsigned lo, hi;
                UNPACK2(lo, hi, acc[ip][0]); v.x = __uint_as_float(e ? hi : lo);
                UNPACK2(lo, hi, acc[ip][1]); v.y = __uint_as_float(e ? hi : lo);
                UNPACK2(lo, hi, acc[ip][2]); v.z = __uint_as_float(e ? hi : lo);
                UNPACK2(lo, hi, acc[ip][3]); v.w = __uint_as_float(e ? hi : lo);
            }
            float s = v.x + v.y + v.z + v.w;
#pragma unroll
            for (int o = 16; o; o >>= 1) s += __shfl_xor_sync(0xffffffffu, s, o);
            float mu = s * (1.0f / 128.0f);

            float dx = v.x - mu, dy = v.y - mu, dz = v.z - mu, dw = v.w - mu;
            float ss = dx * dx + dy * dy + dz * dz + dw * dw;
#pragma unroll
            for (int o = 16; o; o >>= 1) ss += __shfl_xor_sync(0xffffffffu, ss, o);
            float inv = rsqrtf(ss * (1.0f / 128.0f) + 1e-5f);

            v.x = dx * inv * g4.x + b4.x;
            v.y = dy * inv * g4.y + b4.y;
            v.z = dz * inv * g4.z + b4.z;
            v.w = dw * inv * g4.w + b4.w;
            float* dst = g_q + (size_t)(m0 + row) * QDV + n0 + tx * 4;
            *(float4*)dst = v;
        }
    }
}

// ---------------------------------------------------------------------------
// K3a: dots only. Grid (128 tiles, 8 heads, 2 p). Same staging + FMA2 loop
// as round 13 (identical k-order per (p,key,token) chain -> bit-exact scores);
// accumulators stored raw (ull bit pattern) to g_scores. Low regs -> 4 CTA/SM.
// ---------------------------------------------------------------------------
__global__ __launch_bounds__(256, 4) void k3a_dots(const float* __restrict__ keys)
{
    __shared__ float qs[32][33];   // [token][k]
    __shared__ float ks[32][256];  // [k][key] transposed

    const int tid = threadIdx.x;
    const int tx = tid & 31;
    const int wy = tid >> 5;       // warp id: token group
    const int tt = blockIdx.x;
    const int h = blockIdx.y;
    const int p = blockIdx.z;
    const int t0 = tt * 32;

    const int tl = tid >> 3;
    const int kc = (tid & 7) << 2;

    ull acc[4][4];                 // [token][key-pair-quad]
#pragma unroll
    for (int i = 0; i < 4; i++)
#pragma unroll
        for (int jq = 0; jq < 4; jq++) acc[i][jq] = 0ULL;

    const float* qb = g_q + (size_t)(p * HV + h) * DHV;
    const float* kb = keys + ((size_t)(h * NKV + tid) * 2 + p) * DHV;
    for (int kt = 0; kt < DHV; kt += 32) {
        __syncthreads();
        float4 q4 = *(const float4*)(qb + (size_t)(t0 + tl) * QDV + kt + kc);
        qs[tl][kc + 0] = q4.x; qs[tl][kc + 1] = q4.y;
        qs[tl][kc + 2] = q4.z; qs[tl][kc + 3] = q4.w;
        const float* kr = kb + kt;  // key row n = tid (256 keys)
#pragma unroll
        for (int c = 0; c < 8; c++) {
            float4 k4 = *(const float4*)(kr + c * 4);
            ks[c * 4 + 0][tid] = k4.x; ks[c * 4 + 1][tid] = k4.y;
            ks[c * 4 + 2][tid] = k4.z; ks[c * 4 + 3][tid] = k4.w;
        }
        __syncthreads();
#pragma unroll 4
        for (int k = 0; k < 32; k++) {
            ull kv[4];
#pragma unroll
            for (int jq = 0; jq < 4; jq++)
                kv[jq] = *(const ull*)&ks[k][64 * jq + 2 * tx];
#pragma unroll
            for (int i = 0; i < 4; i++) {
                ull qd;
                PACKDUP(qd, qs[wy + 8 * i][k]);
#pragma unroll
                for (int jq = 0; jq < 4; jq++)
                    FMA2(acc[i][jq], qd, kv[jq]);
            }
        }
    }

    // store raw score pairs: ull slot 32*jq + tx holds keys (64jq+2tx, +1)
#pragma unroll
    for (int i = 0; i < 4; i++) {
        const int t = t0 + wy + 8 * i;
        ull* dst = g_scores + ((size_t)(t * HV + h) * 2 + p) * 128;
#pragma unroll
        for (int jq = 0; jq < 4; jq++)
            dst[32 * jq + tx] = acc[i][jq];
    }
}

// ---------------------------------------------------------------------------
// K3b: selection. Warp per (t,h): load both p's 256 scores (raw bits),
// stage-1 top-16 per p (ILP-2 over p — per-p op order/tie-breaks verbatim
// round 9/13), pruned stage-2 (50 cands), softmax. Low regs, high occupancy.
// ---------------------------------------------------------------------------
__global__ __launch_bounds__(256) void k3b_sel()
{
    const int tid = threadIdx.x;
    const int tx = tid & 31;
    const int w = tid >> 5;
    const int gw = blockIdx.x * 8 + w;   // 0..32767
    const int t = gw >> 3, h = gw & 7;

    const ull* sp0 = g_scores + ((size_t)(t * HV + h) * 2 + 0) * 128;
    const ull* sp1 = g_scores + ((size_t)(t * HV + h) * 2 + 1) * 128;

    // v[2jq+e] holds key n = 64jq + 2tx + e  (same slot map as fused kernel)
    float v0[8], v1[8];
#pragma unroll
    for (int jq = 0; jq < 4; jq++) {
        unsigned lo, hi;
        ull d0 = sp0[32 * jq + tx];
        UNPACK2(lo, hi, d0);
        v0[2 * jq + 0] = __uint_as_float(lo);
        v0[2 * jq + 1] = __uint_as_float(hi);
        ull d1 = sp1[32 * jq + tx];
        UNPACK2(lo, hi, d1);
        v1[2 * jq + 0] = __uint_as_float(lo);
        v1[2 * jq + 1] = __uint_as_float(hi);
    }

    // stage 1: top-16 of 256 for BOTH p, interleaved (ILP-2)
    float os0 = 0.f, os1 = 0.f; int oi0 = 0, oi1 = 0;
#pragma unroll 1
    for (int it = 0; it < 16; it++) {
        float bv0 = -INFINITY, bv1 = -INFINITY;
        int bi0 = 0x7fffffff, bi1 = 0x7fffffff;
#pragma unroll
        for (int s = 0; s < 8; s++) {
            int n = ((s >> 1) << 6) + 2 * tx + (s & 1);
            if (v0[s] > bv0) { bv0 = v0[s]; bi0 = n; }
            if (v1[s] > bv1) { bv1 = v1[s]; bi1 = n; }
        }
#pragma unroll
        for (int o = 16; o; o >>= 1) {
            float ov0 = __shfl_xor_sync(0xffffffffu, bv0, o);
            int   on0 = __shfl_xor_sync(0xffffffffu, bi0, o);
            float ov1 = __shfl_xor_sync(0xffffffffu, bv1, o);
            int   on1 = __shfl_xor_sync(0xffffffffu, bi1, o);
            if (ov0 > bv0 || (ov0 == bv0 && on0 < bi0)) { bv0 = ov0; bi0 = on0; }
            if (ov1 > bv1 || (ov1 == bv1 && on1 < bi1)) { bv1 = ov1; bi1 = on1; }
        }
        if (tx == it) { os0 = bv0; oi0 = bi0; os1 = bv1; oi1 = bi1; }
        if (((bi0 >> 1) & 31) == tx) {
            int sl = ((bi0 >> 6) << 1) | (bi0 & 1);
            v0[sl] = -INFINITY;
        }
        if (((bi1 >> 1) & 31) == tx) {
            int sl = ((bi1 >> 6) << 1) | (bi1 & 1);
            v1[sl] = -INFINITY;
        }
    }

    // stage 2: top-16 of 50 pruned candidates (lane l: c=l and c=l+32)
    float v2[2]; int cc2[2];
#pragma unroll
    for (int e = 0; e < 2; e++) {
        int c = tx + 32 * e;
        int ii = c_ci[c], jj = c_cj[c];
        float sxv = __shfl_sync(0xffffffffu, os0, ii);
        float syv = __shfl_sync(0xffffffffu, os1, jj);
        v2[e] = (c < 50) ? sxv + syv : -INFINITY;
        cc2[e] = ii * 16 + jj;
    }
    float os = 0.f; int occ = 0;
#pragma unroll 1
    for (int it = 0; it < 16; it++) {
        float bv = -INFINITY; int bcc = 0x7fffffff;
#pragma unroll
        for (int e = 0; e < 2; e++)
            if (v2[e] > bv || (v2[e] == bv && cc2[e] < bcc)) { bv = v2[e]; bcc = cc2[e]; }
#pragma unroll
        for (int o = 16; o; o >>= 1) {
            float ov = __shfl_xor_sync(0xffffffffu, bv, o);
            int oc2 = __shfl_xor_sync(0xffffffffu, bcc, o);
            if (ov > bv || (ov == bv && oc2 < bcc)) { bv = ov; bcc = oc2; }
        }
        if (tx == it) { os = bv; occ = bcc; }
#pragma unroll
        for (int e = 0; e < 2; e++)
            if (cc2[e] == bcc) v2[e] = -INFINITY;
    }

    // softmax over 16 selected (lane 0 = max) + index gather
    float mx = __shfl_sync(0xffffffffu, os, 0);
    float ev = (tx < 16) ? expf(os - mx) : 0.f;
    float sum = ev;
#pragma unroll
    for (int o = 16; o; o >>= 1) sum += __shfl_xor_sync(0xffffffffu, sum, o);
    int ix = __shfl_sync(0xffffffffu, oi0, (occ >> 4) & 15);
    int iy = __shfl_sync(0xffffffffu, oi1, occ & 15);
    if (tx < 16) {
        int o = (t * HV + h) * KKV + tx;
        g_attn[o] = ev / sum;
        g_vidx[o] = ix * NKV + iy;
    }
}

// ---------------------------------------------------------------------------
// K5: out[t,:] = sum_{m<128} attn[t,m] * values[vidx[t,m], :]
// (at DRAM/L2 bandwidth floor per ncu — unchanged)
// ---------------------------------------------------------------------------
__global__ __launch_bounds__(128) void k5_out(const float* __restrict__ values,
                                              float* __restrict__ out)
{
    __shared__ float sa[128];
    __shared__ int   sv[128];
    const int t = blockIdx.x;
    const int tid = threadIdx.x;
    sa[tid] = g_attn[(size_t)t * 128 + tid];
    sv[tid] = g_vidx[(size_t)t * 128 + tid];
    __syncthreads();

    const float4* V = (const float4*)values;
    float4 acc = make_float4(0.f, 0.f, 0.f, 0.f);
#pragma unroll 8
    for (int m = 0; m < 128; m++) {
        float a = sa[m];
        float4 vv = V[(size_t)sv[m] * 128 + tid];
        acc.x = fmaf(a, vv.x, acc.x);
        acc.y = fmaf(a, vv.y, acc.y);
        acc.z = fmaf(a, vv.z, acc.z);
        acc.w = fmaf(a, vv.w, acc.w);
    }
    ((float4*)out)[(size_t)t * 128 + tid] = acc;
}

// ---------------------------------------------------------------------------
extern "C" void kernel_launch(void* const* d_in, const int* in_sizes, int n_in,
                              void* d_out, int out_size)
{
    const float* x      = (const float*)d_in[0];  // (4,1024,512)
    const float* Wq     = (const float*)d_in[1];  // (2048,512)
    const float* ln_g   = (const float*)d_in[2];  // (128,)
    const float* ln_b   = (const float*)d_in[3];  // (128,)
    const float* keys   = (const float*)d_in[4];  // (8,256,2,128)
    const float* values = (const float*)d_in[5];  // (65536,512)
    float* out = (float*)d_out;                   // (4,1024,512)

    k1_gemm_ln<<<dim3(NTOKS / 64, QDV / 128), 256>>>(x, Wq, ln_g, ln_b);
    k3a_dots<<<dim3(NTOKS / 32, HV, 2), 256>>>(keys);
    k3b_sel<<<NTOKS * HV / 8, 256>>>();
    k5_out<<<NTOKS, 128>>>(values, out);
}